// round 11
// baseline (speedup 1.0000x reference)
#include <cuda_runtime.h>
#include <cstdint>

#define Bb  8
#define Tt  2048
#define Cc  1024
#define HSd 64
#define Mrows (Bb*Tt)
#define NQT  32
#define MAXCH 4
#define NSTG 4             // cp.async pipeline stages
#define KCH  16            // K-chunk
#define APT  20            // A smem pitch (16 + 4 pad -> conflict-free frags)
#define WPT  72            // W smem pitch

// Projected q/k/v (tf32-rounded fp32 bits)
__device__ float g_q[Mrows*HSd];
__device__ float g_k[Mrows*HSd];
__device__ float g_v[Mrows*HSd];
// W, tf32-pre-rounded, layout [k][h]
__device__ float g_wt[3*Cc*HSd];
// Split-KV partials
__device__ float g_pO[Bb*NQT*MAXCH*64*64];
__device__ float g_pm[Bb*NQT*MAXCH*64];
__device__ float g_pl[Bb*NQT*MAXCH*64];

__device__ __forceinline__ uint32_t f2tf(float f) {
    uint32_t u;
    asm("cvt.rna.tf32.f32 %0, %1;" : "=r"(u) : "f"(f));
    return u;
}
__device__ __forceinline__ float tfv(float f) { return __uint_as_float(f2tf(f)); }
__device__ __forceinline__ float ex2(float x) {
    float r;
    asm("ex2.approx.ftz.f32 %0, %1;" : "=f"(r) : "f"(x));
    return r;
}
__device__ __forceinline__ void mma8(float* c, const uint32_t* a, uint32_t b0, uint32_t b1) {
    asm volatile(
        "mma.sync.aligned.m16n8k8.row.col.f32.tf32.tf32.f32 "
        "{%0,%1,%2,%3},{%4,%5,%6,%7},{%8,%9},{%0,%1,%2,%3};"
        : "+f"(c[0]), "+f"(c[1]), "+f"(c[2]), "+f"(c[3])
        : "r"(a[0]), "r"(a[1]), "r"(a[2]), "r"(a[3]), "r"(b0), "r"(b1));
}
__device__ __forceinline__ void cp16(uint32_t dst, const void* src) {
    asm volatile("cp.async.ca.shared.global [%0], [%1], 16;" :: "r"(dst), "l"(src));
}
#define CP_COMMIT() asm volatile("cp.async.commit_group;")
#define CP_WAIT2()  asm volatile("cp.async.wait_group 2;")

// ---------------------------------------------------------------------------
// Prep: tf32-round W, layout unchanged [k][h].
// ---------------------------------------------------------------------------
__global__ __launch_bounds__(256)
void prep_w(const float* __restrict__ Wq, const float* __restrict__ Wk,
            const float* __restrict__ Wv)
{
    const int m = blockIdx.y;
    const float* W = (m == 0) ? Wq : ((m == 1) ? Wk : Wv);
    float* outp = g_wt + (size_t)m * Cc * HSd;
    const int i = (blockIdx.x * 256 + threadIdx.x) * 4;
    float4 v = *(const float4*)(W + i);
    *(float4*)(outp + i) = make_float4(tfv(v.x), tfv(v.y), tfv(v.z), tfv(v.w));
}

// ---------------------------------------------------------------------------
// Projection — 4-stage cp.async stream. CTA: 128 thr (4 warps),
// 128 rows x 64 cols, K-chunks of 16 (64 chunks).
// A: raw fp32 global->smem via cp.async (pitch 20), tf32 cvt AFTER the LDS
//    (identical rounding point -> bit-identical result).
// W: pre-rounded g_wt [k][h] via cp.async (pitch 72), scalar B LDS as r6.
// Prefetch distance 3 chunks; wait_group 2 + one barrier per chunk.
// Smem 59.4 KB dynamic -> 3 CTAs/SM.
// ---------------------------------------------------------------------------
__global__ __launch_bounds__(128, 3)
void proj_kernel(const float* __restrict__ qv, const float* __restrict__ kv,
                 const float* __restrict__ vv)
{
    extern __shared__ float sm[];
    float* Abase = sm;                     // NSTG stages of 128*APT
    float* Wbase = sm + NSTG*128*APT;      // NSTG stages of 16*WPT

    const int m = blockIdx.y;
    const float* in  = (m == 0) ? qv : ((m == 1) ? kv : vv);
    float*       out = (m == 0) ? g_q : ((m == 1) ? g_k : g_v);
    const float* wt  = g_wt + (size_t)m * Cc * HSd;

    const int tid  = threadIdx.x;
    const int wid  = tid >> 5;
    const int lane = tid & 31;
    const int g    = lane >> 2;
    const int tig  = lane & 3;
    const int row0 = blockIdx.x * 128;
    const int m0w  = wid * 32;

    // staging assignments
    const float* arow = in + (size_t)(row0 + tid)*Cc;   // A: one row per thread
    const int wR  = tid >> 3;                           // W: 16 rows, 8 thr/row
    const int wCb = (tid & 7) * 8;                      // 8 floats per thread

#define ISSUE(s, k0)                                                          \
    { const float* ap = arow + (k0);                                          \
      uint32_t ad = (uint32_t)__cvta_generic_to_shared(&Abase[(s)*128*APT + tid*APT]); \
      cp16(ad, ap); cp16(ad + 16, ap + 4);                                    \
      cp16(ad + 32, ap + 8); cp16(ad + 48, ap + 12);                          \
      const float* wp = wt + (size_t)((k0) + wR)*HSd + wCb;                   \
      uint32_t wd = (uint32_t)__cvta_generic_to_shared(&Wbase[(s)*16*WPT + wR*WPT + wCb]); \
      cp16(wd, wp); cp16(wd + 16, wp + 4);                                    \
      CP_COMMIT(); }

    float acc[2][8][4];
#pragma unroll
    for (int mi = 0; mi < 2; mi++)
#pragma unroll
        for (int n = 0; n < 8; n++)
#pragma unroll
            for (int j = 0; j < 4; j++) acc[mi][n][j] = 0.f;

    ISSUE(0, 0);
    ISSUE(1, KCH);
    ISSUE(2, 2*KCH);

    for (int c = 0; c < 64; c++) {
        CP_WAIT2();          // stages <= c complete (this thread)
        __syncthreads();     // visible CTA-wide; prev buffer's readers done

        if (c < 61) { ISSUE((c + 3) & 3, KCH*(c + 3)); }
        else        { CP_COMMIT(); }   // keep group count uniform

        const float* Ac = Abase + (c & 3)*128*APT;
        const float* Wc = Wbase + (c & 3)*16*WPT;

#pragma unroll
        for (int ks = 0; ks < 2; ks++) {
            const int kc = 8*ks + tig;
            uint32_t af0[4] = { f2tf(Ac[(m0w + g     )*APT + kc]),
                                f2tf(Ac[(m0w + g +  8)*APT + kc]),
                                f2tf(Ac[(m0w + g     )*APT + kc + 4]),
                                f2tf(Ac[(m0w + g +  8)*APT + kc + 4]) };
            uint32_t af1[4] = { f2tf(Ac[(m0w + g + 16)*APT + kc]),
                                f2tf(Ac[(m0w + g + 24)*APT + kc]),
                                f2tf(Ac[(m0w + g + 16)*APT + kc + 4]),
                                f2tf(Ac[(m0w + g + 24)*APT + kc + 4]) };
#pragma unroll
            for (int n = 0; n < 8; n++) {
                uint32_t b0 = __float_as_uint(Wc[(8*ks + tig    )*WPT + 8*n + g]);
                uint32_t b1 = __float_as_uint(Wc[(8*ks + tig + 4)*WPT + 8*n + g]);
                mma8(acc[0][n], af0, b0, b1);
                mma8(acc[1][n], af1, b0, b1);
            }
        }
    }

#pragma unroll
    for (int mi = 0; mi < 2; mi++) {
        const int rb = row0 + m0w + mi*16;
#pragma unroll
        for (int n = 0; n < 8; n++) {
            *(float2*)(out + (size_t)(rb + g    )*HSd + 8*n + 2*tig) =
                make_float2(tfv(acc[mi][n][0]), tfv(acc[mi][n][1]));
            *(float2*)(out + (size_t)(rb + g + 8)*HSd + 8*n + 2*tig) =
                make_float2(tfv(acc[mi][n][2]), tfv(acc[mi][n][3]));
        }
    }
#undef ISSUE
}

// ---------------------------------------------------------------------------
// Split-KV flash attention — EXACT round-4/6 version (known good).
// ---------------------------------------------------------------------------
__global__ __launch_bounds__(128, 4)
void attn_kernel(const int* __restrict__ mask, float* __restrict__ out)
{
    __shared__ float KP[64*68];
    __shared__ float Vs[64*72];
    __shared__ int   msk[64];

    const int i = blockIdx.x;
    const int b = i & 7;
    const int r = i >> 3;
    int qb, chunk;
    if (r < 32)      { qb = 24 + (r >> 2);       chunk = r & 3; }
    else if (r < 56) { int t = r - 32; qb = 16 + t/3; chunk = t - 3*(t/3); }
    else if (r < 72) { int t = r - 56; qb = 8 + (t >> 1); chunk = t & 1; }
    else             { qb = r - 72;              chunk = 0; }
    const int nch   = (qb + 8) >> 3;
    const int kb_lo = chunk * 8;
    const int kb_hi = min(kb_lo + 8, qb + 1);

    const int q0   = qb * 64;
    const int tid  = threadIdx.x;
    const int wid  = tid >> 5;
    const int lane = tid & 31;
    const int g    = lane >> 2;
    const int tig  = lane & 3;
    const int m0w  = wid * 16;

    uint32_t qf[8][4];
    const float* qbase = g_q + (size_t)(b*Tt + q0 + m0w)*HSd;
#pragma unroll
    for (int k = 0; k < 8; k++) {
        qf[k][0] = __float_as_uint(qbase[(g    )*HSd + 8*k + tig    ]);
        qf[k][1] = __float_as_uint(qbase[(g + 8)*HSd + 8*k + tig    ]);
        qf[k][2] = __float_as_uint(qbase[(g    )*HSd + 8*k + tig + 4]);
        qf[k][3] = __float_as_uint(qbase[(g + 8)*HSd + 8*k + tig + 4]);
    }

    float o[8][4];
#pragma unroll
    for (int n = 0; n < 8; n++)
#pragma unroll
        for (int j = 0; j < 4; j++) o[n][j] = 0.f;
    float mr0 = -1e30f, mr1 = -1e30f, lr0 = 0.f, lr1 = 0.f;

    const float scale2 = 0.125f * 1.4426950408889634f;
    const int row0g = q0 + m0w + g;
    const int row1g = row0g + 8;

    for (int kb = kb_lo; kb < kb_hi; kb++) {
        const int k0 = kb * 64;
        __syncthreads();

        const float* kg = g_k + (size_t)(b*Tt + k0)*HSd;
        const float* vg = g_v + (size_t)(b*Tt + k0)*HSd;
#pragma unroll
        for (int t = tid; t < 1024; t += 128) {
            int rr = t >> 4, c4 = (t & 15) << 2;
            *(float4*)&KP[rr*68 + c4] = *(const float4*)(kg + rr*HSd + c4);
            *(float4*)&Vs[rr*72 + c4] = *(const float4*)(vg + rr*HSd + c4);
        }
        if (tid < 64) msk[tid] = mask[b*Tt + k0 + tid];
        __syncthreads();

        float s[8][4];
#pragma unroll
        for (int n = 0; n < 8; n++)
#pragma unroll
            for (int j = 0; j < 4; j++) s[n][j] = 0.f;
#pragma unroll
        for (int k = 0; k < 8; k++) {
#pragma unroll
            for (int n = 0; n < 8; n++) {
                uint32_t b0 = __float_as_uint(KP[(8*n + g)*68 + 8*k + tig    ]);
                uint32_t b1 = __float_as_uint(KP[(8*n + g)*68 + 8*k + tig + 4]);
                mma8(s[n], qf[k], b0, b1);
            }
        }

        const bool diag = (kb == qb);
#pragma unroll
        for (int n = 0; n < 8; n++) {
            int cl = 8*n + 2*tig;
            int2 mm = *(const int2*)&msk[cl];
            int c0 = k0 + cl, c1 = c0 + 1;
            bool v00 = (mm.x != 0) && (!diag || c0 <= row0g);
            bool v01 = (mm.y != 0) && (!diag || c1 <= row0g);
            bool v10 = (mm.x != 0) && (!diag || c0 <= row1g);
            bool v11 = (mm.y != 0) && (!diag || c1 <= row1g);
            s[n][0] = v00 ? s[n][0]*scale2 : -1e30f;
            s[n][1] = v01 ? s[n][1]*scale2 : -1e30f;
            s[n][2] = v10 ? s[n][2]*scale2 : -1e30f;
            s[n][3] = v11 ? s[n][3]*scale2 : -1e30f;
        }

        {
            float m0 = -1e30f, m1 = -1e30f;
#pragma unroll
            for (int n = 0; n < 8; n++) {
                m0 = fmaxf(m0, fmaxf(s[n][0], s[n][1]));
                m1 = fmaxf(m1, fmaxf(s[n][2], s[n][3]));
            }
#pragma unroll
            for (int off = 1; off < 4; off <<= 1) {
                m0 = fmaxf(m0, __shfl_xor_sync(0xffffffffu, m0, off));
                m1 = fmaxf(m1, __shfl_xor_sync(0xffffffffu, m1, off));
            }
            float mn0 = fmaxf(mr0, m0), mn1 = fmaxf(mr1, m1);
            float al0 = ex2(mr0 - mn0), al1 = ex2(mr1 - mn1);
            float ls0 = 0.f, ls1 = 0.f;
#pragma unroll
            for (int n = 0; n < 8; n++) {
                s[n][0] = ex2(s[n][0] - mn0);
                s[n][1] = ex2(s[n][1] - mn0);
                s[n][2] = ex2(s[n][2] - mn1);
                s[n][3] = ex2(s[n][3] - mn1);
                ls0 += s[n][0] + s[n][1];
                ls1 += s[n][2] + s[n][3];
            }
#pragma unroll
            for (int off = 1; off < 4; off <<= 1) {
                ls0 += __shfl_xor_sync(0xffffffffu, ls0, off);
                ls1 += __shfl_xor_sync(0xffffffffu, ls1, off);
            }
            lr0 = lr0*al0 + ls0;  mr0 = mn0;
            lr1 = lr1*al1 + ls1;  mr1 = mn1;
#pragma unroll
            for (int n = 0; n < 8; n++) {
                o[n][0] *= al0; o[n][1] *= al0;
                o[n][2] *= al1; o[n][3] *= al1;
            }
        }

        __syncthreads();
#pragma unroll
        for (int n = 0; n < 8; n++) {
            float2 p0 = make_float2(tfv(s[n][0]), tfv(s[n][1]));
            float2 p1 = make_float2(tfv(s[n][2]), tfv(s[n][3]));
            *(float2*)&KP[(m0w + g    )*68 + 8*n + 2*tig] = p0;
            *(float2*)&KP[(m0w + g + 8)*68 + 8*n + 2*tig] = p1;
        }
        __syncwarp();

#pragma unroll
        for (int k = 0; k < 8; k++) {
            uint32_t af[4];
            af[0] = __float_as_uint(KP[(m0w + g    )*68 + 8*k + tig    ]);
            af[1] = __float_as_uint(KP[(m0w + g + 8)*68 + 8*k + tig    ]);
            af[2] = __float_as_uint(KP[(m0w + g    )*68 + 8*k + tig + 4]);
            af[3] = __float_as_uint(KP[(m0w + g + 8)*68 + 8*k + tig + 4]);
#pragma unroll
            for (int n = 0; n < 8; n++) {
                uint32_t b0 = __float_as_uint(Vs[(8*k + tig    )*72 + 8*n + g]);
                uint32_t b1 = __float_as_uint(Vs[(8*k + tig + 4)*72 + 8*n + g]);
                mma8(o[n], af, b0, b1);
            }
        }
    }

    if (nch == 1) {
        const float inv0 = 1.0f / lr0, inv1 = 1.0f / lr1;
        float* obase = out + (size_t)(b*Tt + q0 + m0w)*HSd;
#pragma unroll
        for (int n = 0; n < 8; n++) {
            *(float2*)(obase + (g    )*HSd + 8*n + 2*tig) =
                make_float2(o[n][0]*inv0, o[n][1]*inv0);
            *(float2*)(obase + (g + 8)*HSd + 8*n + 2*tig) =
                make_float2(o[n][2]*inv1, o[n][3]*inv1);
        }
    } else {
        const size_t idx = (size_t)((b*NQT + qb)*MAXCH + chunk);
        float* pO = g_pO + idx*4096;
#pragma unroll
        for (int n = 0; n < 8; n++) {
            *(float2*)&pO[(m0w + g    )*64 + 8*n + 2*tig] =
                make_float2(o[n][0], o[n][1]);
            *(float2*)&pO[(m0w + g + 8)*64 + 8*n + 2*tig] =
                make_float2(o[n][2], o[n][3]);
        }
        if (tig == 0) {
            g_pm[idx*64 + m0w + g    ] = mr0;
            g_pl[idx*64 + m0w + g    ] = lr0;
            g_pm[idx*64 + m0w + g + 8] = mr1;
            g_pl[idx*64 + m0w + g + 8] = lr1;
        }
    }
}

// ---------------------------------------------------------------------------
// Combine partials for qb >= 8. Grid (24, 8) x 512 thr.
// ---------------------------------------------------------------------------
__global__ __launch_bounds__(512)
void combine_kernel(float* __restrict__ out)
{
    const int qb  = 8 + blockIdx.x;
    const int b   = blockIdx.y;
    const int nch = (qb + 8) >> 3;
    const int t   = threadIdx.x;
    const int row = t >> 3;
    const int oc  = (t & 7) * 8;
    const int base = (b*NQT + qb)*MAXCH;

    float mg = -1e30f;
    for (int i = 0; i < nch; i++)
        mg = fmaxf(mg, g_pm[(base + i)*64 + row]);

    float l = 0.f;
    float4 acc[2];
    acc[0] = make_float4(0.f, 0.f, 0.f, 0.f);
    acc[1] = make_float4(0.f, 0.f, 0.f, 0.f);

    for (int i = 0; i < nch; i++) {
        float w = ex2(g_pm[(base + i)*64 + row] - mg);
        l += w * g_pl[(base + i)*64 + row];
        const float4* src = (const float4*)&g_pO[(size_t)(base + i)*4096 + row*64 + oc];
#pragma unroll
        for (int j = 0; j < 2; j++) {
            float4 v = src[j];
            acc[j].x += w*v.x; acc[j].y += w*v.y;
            acc[j].z += w*v.z; acc[j].w += w*v.w;
        }
    }

    const float inv = 1.0f / l;
    float4* dst = (float4*)(out + (size_t)(b*Tt + qb*64 + row)*HSd + oc);
#pragma unroll
    for (int j = 0; j < 2; j++)
        dst[j] = make_float4(acc[j].x*inv, acc[j].y*inv, acc[j].z*inv, acc[j].w*inv);
}

// ---------------------------------------------------------------------------
extern "C" void kernel_launch(void* const* d_in, const int* in_sizes, int n_in,
                              void* d_out, int out_size)
{
    const float* q_vec = (const float*)d_in[0];
    const float* k_vec = (const float*)d_in[1];
    const float* v_vec = (const float*)d_in[2];
    const int*   mask  = (const int*)  d_in[3];
    const float* Wq    = (const float*)d_in[4];
    const float* Wk    = (const float*)d_in[5];
    const float* Wv    = (const float*)d_in[6];
    float* out = (float*)d_out;

    const int proj_smem = (NSTG*128*APT + NSTG*16*WPT) * 4;   // 59392 B
    cudaFuncSetAttribute(proj_kernel,
                         cudaFuncAttributeMaxDynamicSharedMemorySize, proj_smem);

    prep_w<<<dim3(Cc*HSd/1024, 3), 256>>>(Wq, Wk, Wv);
    proj_kernel<<<dim3(Mrows/128, 3), 128, proj_smem>>>(q_vec, k_vec, v_vec);
    attn_kernel<<<640, 128>>>(mask, out);
    combine_kernel<<<dim3(24, 8), 512>>>(out);
}

// round 12
// speedup vs baseline: 1.1962x; 1.1962x over previous
#include <cuda_runtime.h>
#include <cstdint>

#define Bb  8
#define Tt  2048
#define Cc  1024
#define HSd 64
#define Mrows (Bb*Tt)
#define NQT  16            // 128-row Q tiles per batch
#define MAXCH 4
#define PPITCH 40          // proj smem pitch (r6)

// Projected q/k/v (tf32-rounded fp32 bits)
__device__ float g_q[Mrows*HSd];
__device__ float g_k[Mrows*HSd];
__device__ float g_v[Mrows*HSd];
// W, tf32-pre-rounded, layout [k][h]
__device__ float g_wt[3*Cc*HSd];
// Split-KV partials (128-row Q tiles)
__device__ float g_pO[Bb*NQT*MAXCH*128*64];
__device__ float g_pm[Bb*NQT*MAXCH*128];
__device__ float g_pl[Bb*NQT*MAXCH*128];

__device__ __forceinline__ uint32_t f2tf(float f) {
    uint32_t u;
    asm("cvt.rna.tf32.f32 %0, %1;" : "=r"(u) : "f"(f));
    return u;
}
__device__ __forceinline__ float tfv(float f) { return __uint_as_float(f2tf(f)); }
__device__ __forceinline__ float ex2(float x) {
    float r;
    asm("ex2.approx.ftz.f32 %0, %1;" : "=f"(r) : "f"(x));
    return r;
}
__device__ __forceinline__ void mma8(float* c, const uint32_t* a, uint32_t b0, uint32_t b1) {
    asm volatile(
        "mma.sync.aligned.m16n8k8.row.col.f32.tf32.tf32.f32 "
        "{%0,%1,%2,%3},{%4,%5,%6,%7},{%8,%9},{%0,%1,%2,%3};"
        : "+f"(c[0]), "+f"(c[1]), "+f"(c[2]), "+f"(c[3])
        : "r"(a[0]), "r"(a[1]), "r"(a[2]), "r"(a[3]), "r"(b0), "r"(b1));
}

// ---------------------------------------------------------------------------
// Prep: tf32-round W, layout unchanged [k][h].  (r6 verbatim)
// ---------------------------------------------------------------------------
__global__ __launch_bounds__(256)
void prep_w(const float* __restrict__ Wq, const float* __restrict__ Wk,
            const float* __restrict__ Wv)
{
    const int m = blockIdx.y;
    const float* W = (m == 0) ? Wq : ((m == 1) ? Wk : Wv);
    float* outp = g_wt + (size_t)m * Cc * HSd;
    const int i = (blockIdx.x * 256 + threadIdx.x) * 4;
    float4 v = *(const float4*)(W + i);
    *(float4*)(outp + i) = make_float4(tfv(v.x), tfv(v.y), tfv(v.z), tfv(v.w));
}

// ---------------------------------------------------------------------------
// Projection — EXACT round-6 version (best measured: 139.8 total).
// ---------------------------------------------------------------------------
__global__ __launch_bounds__(128, 3)
void proj_kernel(const float* __restrict__ qv, const float* __restrict__ kv,
                 const float* __restrict__ vv)
{
    extern __shared__ float sm[];
    float* As0 = sm;
    float* As1 = sm + 128*PPITCH;
    float* Ws0 = sm + 2*128*PPITCH;
    float* Ws1 = sm + 2*128*PPITCH + 32*72;

    const int m = blockIdx.y;
    const float* in  = (m == 0) ? qv : ((m == 1) ? kv : vv);
    float*       out = (m == 0) ? g_q : ((m == 1) ? g_k : g_v);
    const float* wt  = g_wt + (size_t)m * Cc * HSd;

    const int tid  = threadIdx.x;
    const int wid  = tid >> 5;
    const int lane = tid & 31;
    const int g    = lane >> 2;
    const int tig  = lane & 3;
    const int row0 = blockIdx.x * 128;
    const int m0w  = wid * 32;

    const int aR = tid >> 2;
    const int aC = (tid & 3) * 8;
    const int wR = tid >> 2;
    const int wC = (tid & 3) * 16;

    float4 pa[8];
    float4 pw[4];

#define LDA(k0)                                                               \
    { _Pragma("unroll") for (int i = 0; i < 4; i++) {                         \
        const float* p = in + (size_t)(row0 + aR + 32*i)*Cc + (k0) + aC;      \
        pa[2*i]   = *(const float4*)p;                                        \
        pa[2*i+1] = *(const float4*)(p + 4); } }

#define LDWm(k0)                                                              \
    { const float* p = wt + (size_t)((k0) + wR)*HSd + wC;                     \
      _Pragma("unroll") for (int i = 0; i < 4; i++)                           \
          pw[i] = *(const float4*)(p + 4*i); }

#define STAB(buf)                                                             \
    { _Pragma("unroll") for (int i = 0; i < 4; i++) {                         \
        float4 a = pa[2*i], b = pa[2*i+1];                                    \
        *(float4*)&(buf)[(aR + 32*i)*PPITCH + aC] =                           \
            make_float4(tfv(a.x), tfv(b.x), tfv(a.y), tfv(b.y));              \
        *(float4*)&(buf)[(aR + 32*i)*PPITCH + aC + 4] =                       \
            make_float4(tfv(a.z), tfv(b.z), tfv(a.w), tfv(b.w)); } }

#define STWB(buf)                                                             \
    { _Pragma("unroll") for (int i = 0; i < 4; i++)                           \
        *(float4*)&(buf)[wR*72 + wC + 4*i] = pw[i]; }

    float acc[2][8][4];
#pragma unroll
    for (int mi = 0; mi < 2; mi++)
#pragma unroll
        for (int n = 0; n < 8; n++)
#pragma unroll
            for (int j = 0; j < 4; j++) acc[mi][n][j] = 0.f;

    LDA(0); LDWm(0);
    STAB(As0); STWB(Ws0);
    __syncthreads();

    for (int c = 0; c < 32; c++) {
        const int cur = c & 1;
        float* Acur = cur ? As1 : As0;
        float* Wcur = cur ? Ws1 : Ws0;
        float* Anxt = cur ? As0 : As1;
        float* Wnxt = cur ? Ws0 : Ws1;

        if (c < 31) { LDA(32*(c+1)); LDWm(32*(c+1)); }

#pragma unroll
        for (int ks = 0; ks < 4; ks++) {
            float2 a0 = *(const float2*)&Acur[(m0w + g     )*PPITCH + 8*ks + 2*tig];
            float2 a1 = *(const float2*)&Acur[(m0w + g +  8)*PPITCH + 8*ks + 2*tig];
            float2 a2 = *(const float2*)&Acur[(m0w + g + 16)*PPITCH + 8*ks + 2*tig];
            float2 a3 = *(const float2*)&Acur[(m0w + g + 24)*PPITCH + 8*ks + 2*tig];
            uint32_t af0[4] = { __float_as_uint(a0.x), __float_as_uint(a1.x),
                                __float_as_uint(a0.y), __float_as_uint(a1.y) };
            uint32_t af1[4] = { __float_as_uint(a2.x), __float_as_uint(a3.x),
                                __float_as_uint(a2.y), __float_as_uint(a3.y) };
#pragma unroll
            for (int n = 0; n < 8; n++) {
                uint32_t b0 = __float_as_uint(Wcur[(8*ks + tig    )*72 + 8*n + g]);
                uint32_t b1 = __float_as_uint(Wcur[(8*ks + tig + 4)*72 + 8*n + g]);
                mma8(acc[0][n], af0, b0, b1);
                mma8(acc[1][n], af1, b0, b1);
            }
        }
        if (c < 31) { STAB(Anxt); STWB(Wnxt); }
        __syncthreads();
    }

#pragma unroll
    for (int mi = 0; mi < 2; mi++) {
        const int rb = row0 + m0w + mi*16;
#pragma unroll
        for (int n = 0; n < 8; n++) {
            *(float2*)(out + (size_t)(rb + g    )*HSd + 8*n + 2*tig) =
                make_float2(tfv(acc[mi][n][0]), tfv(acc[mi][n][1]));
            *(float2*)(out + (size_t)(rb + g + 8)*HSd + 8*n + 2*tig) =
                make_float2(tfv(acc[mi][n][2]), tfv(acc[mi][n][3]));
        }
    }
#undef LDA
#undef LDWm
#undef STAB
#undef STWB
}

// ---------------------------------------------------------------------------
// Split-KV flash attention — 128-row Q tiles, 8 warps (256 thr), 2 CTAs/SM.
// Per-warp inner code identical to the proven r4/r6 version (16 rows/warp).
// K/V loaded once per 128 Q rows (half the traffic of the 64-row version).
// KP: 128x68 (K tile in rows 0..63, P uses all 128 rows). Vs: 64x72.
// Grid 320 = 8 batches x 40 chunks (<=8 KV tiles each), heavy chunks first.
// ---------------------------------------------------------------------------
__global__ __launch_bounds__(256, 2)
void attn_kernel(const int* __restrict__ mask, float* __restrict__ out)
{
    extern __shared__ float asm_[];
    float* KP = asm_;                 // 128*68
    float* Vs = asm_ + 128*68;        // 64*72
    __shared__ int msk[64];

    const int i = blockIdx.x;
    const int b = i & 7;
    const int r = 39 - (i >> 3);      // heavy (large qb) first
    int qb, chunk;
    if (r < 4)       { qb = r;                        chunk = 0; }
    else if (r < 12) { int t = r - 4;  qb = 4  + (t >> 1); chunk = t & 1; }
    else if (r < 24) { int t = r - 12; qb = 8  + t/3;      chunk = t - 3*(t/3); }
    else             { int t = r - 24; qb = 12 + (t >> 2); chunk = t & 3; }
    const int nch   = (2*qb + 9) >> 3;          // 1..4
    const int kb_lo = chunk * 8;
    const int kb_hi = min(kb_lo + 8, 2*qb + 2);

    const int q0   = qb * 128;
    const int tid  = threadIdx.x;
    const int wid  = tid >> 5;        // 0..7
    const int lane = tid & 31;
    const int g    = lane >> 2;
    const int tig  = lane & 3;
    const int m0w  = wid * 16;        // 0..112

    uint32_t qf[8][4];
    const float* qbase = g_q + (size_t)(b*Tt + q0 + m0w)*HSd;
#pragma unroll
    for (int k = 0; k < 8; k++) {
        qf[k][0] = __float_as_uint(qbase[(g    )*HSd + 8*k + tig    ]);
        qf[k][1] = __float_as_uint(qbase[(g + 8)*HSd + 8*k + tig    ]);
        qf[k][2] = __float_as_uint(qbase[(g    )*HSd + 8*k + tig + 4]);
        qf[k][3] = __float_as_uint(qbase[(g + 8)*HSd + 8*k + tig + 4]);
    }

    float o[8][4];
#pragma unroll
    for (int n = 0; n < 8; n++)
#pragma unroll
        for (int j = 0; j < 4; j++) o[n][j] = 0.f;
    float mr0 = -1e30f, mr1 = -1e30f, lr0 = 0.f, lr1 = 0.f;

    const float scale2 = 0.125f * 1.4426950408889634f;
    const int row0g = q0 + m0w + g;
    const int row1g = row0g + 8;

    for (int kb = kb_lo; kb < kb_hi; kb++) {
        const int k0 = kb * 64;
        __syncthreads();   // previous tile's P/V/msk readers done

        const float* kg = g_k + (size_t)(b*Tt + k0)*HSd;
        const float* vg = g_v + (size_t)(b*Tt + k0)*HSd;
#pragma unroll
        for (int t = tid; t < 1024; t += 256) {
            int rr = t >> 4, c4 = (t & 15) << 2;
            *(float4*)&KP[rr*68 + c4] = *(const float4*)(kg + rr*HSd + c4);
            *(float4*)&Vs[rr*72 + c4] = *(const float4*)(vg + rr*HSd + c4);
        }
        if (tid < 64) msk[tid] = mask[b*Tt + k0 + tid];
        __syncthreads();

        // ---- S = Q K^T ----
        float s[8][4];
#pragma unroll
        for (int n = 0; n < 8; n++)
#pragma unroll
            for (int j = 0; j < 4; j++) s[n][j] = 0.f;
#pragma unroll
        for (int k = 0; k < 8; k++) {
#pragma unroll
            for (int n = 0; n < 8; n++) {
                uint32_t b0 = __float_as_uint(KP[(8*n + g)*68 + 8*k + tig    ]);
                uint32_t b1 = __float_as_uint(KP[(8*n + g)*68 + 8*k + tig + 4]);
                mma8(s[n], qf[k], b0, b1);
            }
        }

        // ---- scale (log2) + causal/pad mask ----
        const bool diag = (k0 >= q0);   // last two KV tiles overlap the diagonal
#pragma unroll
        for (int n = 0; n < 8; n++) {
            int cl = 8*n + 2*tig;
            int2 mm = *(const int2*)&msk[cl];
            int c0 = k0 + cl, c1 = c0 + 1;
            bool v00 = (mm.x != 0) && (!diag || c0 <= row0g);
            bool v01 = (mm.y != 0) && (!diag || c1 <= row0g);
            bool v10 = (mm.x != 0) && (!diag || c0 <= row1g);
            bool v11 = (mm.y != 0) && (!diag || c1 <= row1g);
            s[n][0] = v00 ? s[n][0]*scale2 : -1e30f;
            s[n][1] = v01 ? s[n][1]*scale2 : -1e30f;
            s[n][2] = v10 ? s[n][2]*scale2 : -1e30f;
            s[n][3] = v11 ? s[n][3]*scale2 : -1e30f;
        }

        // ---- online softmax, base-2 ----
        {
            float m0 = -1e30f, m1 = -1e30f;
#pragma unroll
            for (int n = 0; n < 8; n++) {
                m0 = fmaxf(m0, fmaxf(s[n][0], s[n][1]));
                m1 = fmaxf(m1, fmaxf(s[n][2], s[n][3]));
            }
#pragma unroll
            for (int off = 1; off < 4; off <<= 1) {
                m0 = fmaxf(m0, __shfl_xor_sync(0xffffffffu, m0, off));
                m1 = fmaxf(m1, __shfl_xor_sync(0xffffffffu, m1, off));
            }
            float mn0 = fmaxf(mr0, m0), mn1 = fmaxf(mr1, m1);
            float al0 = ex2(mr0 - mn0), al1 = ex2(mr1 - mn1);
            float ls0 = 0.f, ls1 = 0.f;
#pragma unroll
            for (int n = 0; n < 8; n++) {
                s[n][0] = ex2(s[n][0] - mn0);
                s[n][1] = ex2(s[n][1] - mn0);
                s[n][2] = ex2(s[n][2] - mn1);
                s[n][3] = ex2(s[n][3] - mn1);
                ls0 += s[n][0] + s[n][1];
                ls1 += s[n][2] + s[n][3];
            }
#pragma unroll
            for (int off = 1; off < 4; off <<= 1) {
                ls0 += __shfl_xor_sync(0xffffffffu, ls0, off);
                ls1 += __shfl_xor_sync(0xffffffffu, ls1, off);
            }
            lr0 = lr0*al0 + ls0;  mr0 = mn0;
            lr1 = lr1*al1 + ls1;  mr1 = mn1;
#pragma unroll
            for (int n = 0; n < 8; n++) {
                o[n][0] *= al0; o[n][1] *= al0;
                o[n][2] *= al1; o[n][3] *= al1;
            }
        }

        __syncthreads();   // all warps done reading K rows of KP
        // ---- P (tf32) into own rows of KP; warp-local visibility only ----
#pragma unroll
        for (int n = 0; n < 8; n++) {
            float2 p0 = make_float2(tfv(s[n][0]), tfv(s[n][1]));
            float2 p1 = make_float2(tfv(s[n][2]), tfv(s[n][3]));
            *(float2*)&KP[(m0w + g    )*68 + 8*n + 2*tig] = p0;
            *(float2*)&KP[(m0w + g + 8)*68 + 8*n + 2*tig] = p1;
        }
        __syncwarp();

        // ---- O += P V ----
#pragma unroll
        for (int k = 0; k < 8; k++) {
            uint32_t af[4];
            af[0] = __float_as_uint(KP[(m0w + g    )*68 + 8*k + tig    ]);
            af[1] = __float_as_uint(KP[(m0w + g + 8)*68 + 8*k + tig    ]);
            af[2] = __float_as_uint(KP[(m0w + g    )*68 + 8*k + tig + 4]);
            af[3] = __float_as_uint(KP[(m0w + g + 8)*68 + 8*k + tig + 4]);
#pragma unroll
            for (int n = 0; n < 8; n++) {
                uint32_t b0 = __float_as_uint(Vs[(8*k + tig    )*72 + 8*n + g]);
                uint32_t b1 = __float_as_uint(Vs[(8*k + tig + 4)*72 + 8*n + g]);
                mma8(o[n], af, b0, b1);
            }
        }
    }

    // ---- epilogue ----
    if (nch == 1) {
        const float inv0 = 1.0f / lr0, inv1 = 1.0f / lr1;
        float* obase = out + (size_t)(b*Tt + q0 + m0w)*HSd;
#pragma unroll
        for (int n = 0; n < 8; n++) {
            *(float2*)(obase + (g    )*HSd + 8*n + 2*tig) =
                make_float2(o[n][0]*inv0, o[n][1]*inv0);
            *(float2*)(obase + (g + 8)*HSd + 8*n + 2*tig) =
                make_float2(o[n][2]*inv1, o[n][3]*inv1);
        }
    } else {
        const size_t idx = (size_t)((b*NQT + qb)*MAXCH + chunk);
        float* pO = g_pO + idx*8192;
#pragma unroll
        for (int n = 0; n < 8; n++) {
            *(float2*)&pO[(m0w + g    )*64 + 8*n + 2*tig] =
                make_float2(o[n][0], o[n][1]);
            *(float2*)&pO[(m0w + g + 8)*64 + 8*n + 2*tig] =
                make_float2(o[n][2], o[n][3]);
        }
        if (tig == 0) {
            g_pm[idx*128 + m0w + g    ] = mr0;
            g_pl[idx*128 + m0w + g    ] = lr0;
            g_pm[idx*128 + m0w + g + 8] = mr1;
            g_pl[idx*128 + m0w + g + 8] = lr1;
        }
    }
}

// ---------------------------------------------------------------------------
// Combine partials for qb >= 4 (2..4 chunks). Grid (12, 8) x 512 thr.
// ---------------------------------------------------------------------------
__global__ __launch_bounds__(512)
void combine_kernel(float* __restrict__ out)
{
    const int qb  = 4 + blockIdx.x;
    const int b   = blockIdx.y;
    const int nch = (2*qb + 9) >> 3;
    const int t   = threadIdx.x;
    const int row = t >> 2;           // 0..127
    const int oc  = (t & 3) * 16;     // 0,16,32,48
    const int base = (b*NQT + qb)*MAXCH;

    float mg = -1e30f;
    for (int i = 0; i < nch; i++)
        mg = fmaxf(mg, g_pm[(base + i)*128 + row]);

    float l = 0.f;
    float4 acc[4];
#pragma unroll
    for (int j = 0; j < 4; j++) acc[j] = make_float4(0.f, 0.f, 0.f, 0.f);

    for (int i = 0; i < nch; i++) {
        float w = ex2(g_pm[(base + i)*128 + row] - mg);
        l += w * g_pl[(base + i)*128 + row];
        const float4* src = (const float4*)&g_pO[(size_t)(base + i)*8192 + row*64 + oc];
#pragma unroll
        for (int j = 0; j < 4; j++) {
            float4 v = src[j];
            acc[j].x += w*v.x; acc[j].y += w*v.y;
            acc[j].z += w*v.z; acc[j].w += w*v.w;
        }
    }

    const float inv = 1.0f / l;
    float4* dst = (float4*)(out + (size_t)(b*Tt + qb*128 + row)*HSd + oc);
#pragma unroll
    for (int j = 0; j < 4; j++)
        dst[j] = make_float4(acc[j].x*inv, acc[j].y*inv, acc[j].z*inv, acc[j].w*inv);
}

// ---------------------------------------------------------------------------
extern "C" void kernel_launch(void* const* d_in, const int* in_sizes, int n_in,
                              void* d_out, int out_size)
{
    const float* q_vec = (const float*)d_in[0];
    const float* k_vec = (const float*)d_in[1];
    const float* v_vec = (const float*)d_in[2];
    const int*   mask  = (const int*)  d_in[3];
    const float* Wq    = (const float*)d_in[4];
    const float* Wk    = (const float*)d_in[5];
    const float* Wv    = (const float*)d_in[6];
    float* out = (float*)d_out;

    const int proj_smem = (2*128*PPITCH + 2*32*72) * 4;   // 59392 B
    cudaFuncSetAttribute(proj_kernel,
                         cudaFuncAttributeMaxDynamicSharedMemorySize, proj_smem);
    const int attn_smem = (128*68 + 64*72) * 4;           // 53248 B
    cudaFuncSetAttribute(attn_kernel,
                         cudaFuncAttributeMaxDynamicSharedMemorySize, attn_smem);

    prep_w<<<dim3(Cc*HSd/1024, 3), 256>>>(Wq, Wk, Wv);
    proj_kernel<<<dim3(Mrows/128, 3), 128, proj_smem>>>(q_vec, k_vec, v_vec);
    attn_kernel<<<320, 256, attn_smem>>>(mask, out);
    combine_kernel<<<dim3(12, 8), 512>>>(out);
}

// round 13
// speedup vs baseline: 1.2045x; 1.0069x over previous
#include <cuda_runtime.h>
#include <cstdint>

#define Bb  8
#define Tt  2048
#define Cc  1024
#define HSd 64
#define Mrows (Bb*Tt)
#define NQT  16            // 128-row Q tiles per batch
#define MAXCH 4
#define PPITCH 40          // proj smem pitch (r6)

// Projected q/k/v (tf32-rounded fp32 bits)
__device__ float g_q[Mrows*HSd];
__device__ float g_k[Mrows*HSd];
__device__ float g_v[Mrows*HSd];
// W, tf32-pre-rounded, layout [k][h]
__device__ float g_wt[3*Cc*HSd];
// Split-KV partials (128-row Q tiles)
__device__ float g_pO[Bb*NQT*MAXCH*128*64];
__device__ float g_pm[Bb*NQT*MAXCH*128];
__device__ float g_pl[Bb*NQT*MAXCH*128];

__device__ __forceinline__ uint32_t f2tf(float f) {
    uint32_t u;
    asm("cvt.rna.tf32.f32 %0, %1;" : "=r"(u) : "f"(f));
    return u;
}
__device__ __forceinline__ float tfv(float f) { return __uint_as_float(f2tf(f)); }
__device__ __forceinline__ float ex2(float x) {
    float r;
    asm("ex2.approx.ftz.f32 %0, %1;" : "=f"(r) : "f"(x));
    return r;
}
__device__ __forceinline__ void mma8(float* c, const uint32_t* a, uint32_t b0, uint32_t b1) {
    asm volatile(
        "mma.sync.aligned.m16n8k8.row.col.f32.tf32.tf32.f32 "
        "{%0,%1,%2,%3},{%4,%5,%6,%7},{%8,%9},{%0,%1,%2,%3};"
        : "+f"(c[0]), "+f"(c[1]), "+f"(c[2]), "+f"(c[3])
        : "r"(a[0]), "r"(a[1]), "r"(a[2]), "r"(a[3]), "r"(b0), "r"(b1));
}
__device__ __forceinline__ void cp16(uint32_t dst, const void* src) {
    asm volatile("cp.async.ca.shared.global [%0], [%1], 16;" :: "r"(dst), "l"(src));
}
#define CP_COMMIT() asm volatile("cp.async.commit_group;")
#define CP_WAIT0()  asm volatile("cp.async.wait_group 0;")

// ---------------------------------------------------------------------------
// Prep: tf32-round W, layout unchanged [k][h].  (r6 verbatim)
// ---------------------------------------------------------------------------
__global__ __launch_bounds__(256)
void prep_w(const float* __restrict__ Wq, const float* __restrict__ Wk,
            const float* __restrict__ Wv)
{
    const int m = blockIdx.y;
    const float* W = (m == 0) ? Wq : ((m == 1) ? Wk : Wv);
    float* outp = g_wt + (size_t)m * Cc * HSd;
    const int i = (blockIdx.x * 256 + threadIdx.x) * 4;
    float4 v = *(const float4*)(W + i);
    *(float4*)(outp + i) = make_float4(tfv(v.x), tfv(v.y), tfv(v.z), tfv(v.w));
}

// ---------------------------------------------------------------------------
// Projection — EXACT round-6 version (frozen; best measured).
// ---------------------------------------------------------------------------
__global__ __launch_bounds__(128, 3)
void proj_kernel(const float* __restrict__ qv, const float* __restrict__ kv,
                 const float* __restrict__ vv)
{
    extern __shared__ float sm[];
    float* As0 = sm;
    float* As1 = sm + 128*PPITCH;
    float* Ws0 = sm + 2*128*PPITCH;
    float* Ws1 = sm + 2*128*PPITCH + 32*72;

    const int m = blockIdx.y;
    const float* in  = (m == 0) ? qv : ((m == 1) ? kv : vv);
    float*       out = (m == 0) ? g_q : ((m == 1) ? g_k : g_v);
    const float* wt  = g_wt + (size_t)m * Cc * HSd;

    const int tid  = threadIdx.x;
    const int wid  = tid >> 5;
    const int lane = tid & 31;
    const int g    = lane >> 2;
    const int tig  = lane & 3;
    const int row0 = blockIdx.x * 128;
    const int m0w  = wid * 32;

    const int aR = tid >> 2;
    const int aC = (tid & 3) * 8;
    const int wR = tid >> 2;
    const int wC = (tid & 3) * 16;

    float4 pa[8];
    float4 pw[4];

#define LDA(k0)                                                               \
    { _Pragma("unroll") for (int i = 0; i < 4; i++) {                         \
        const float* p = in + (size_t)(row0 + aR + 32*i)*Cc + (k0) + aC;      \
        pa[2*i]   = *(const float4*)p;                                        \
        pa[2*i+1] = *(const float4*)(p + 4); } }

#define LDWm(k0)                                                              \
    { const float* p = wt + (size_t)((k0) + wR)*HSd + wC;                     \
      _Pragma("unroll") for (int i = 0; i < 4; i++)                           \
          pw[i] = *(const float4*)(p + 4*i); }

#define STAB(buf)                                                             \
    { _Pragma("unroll") for (int i = 0; i < 4; i++) {                         \
        float4 a = pa[2*i], b = pa[2*i+1];                                    \
        *(float4*)&(buf)[(aR + 32*i)*PPITCH + aC] =                           \
            make_float4(tfv(a.x), tfv(b.x), tfv(a.y), tfv(b.y));              \
        *(float4*)&(buf)[(aR + 32*i)*PPITCH + aC + 4] =                       \
            make_float4(tfv(a.z), tfv(b.z), tfv(a.w), tfv(b.w)); } }

#define STWB(buf)                                                             \
    { _Pragma("unroll") for (int i = 0; i < 4; i++)                           \
        *(float4*)&(buf)[wR*72 + wC + 4*i] = pw[i]; }

    float acc[2][8][4];
#pragma unroll
    for (int mi = 0; mi < 2; mi++)
#pragma unroll
        for (int n = 0; n < 8; n++)
#pragma unroll
            for (int j = 0; j < 4; j++) acc[mi][n][j] = 0.f;

    LDA(0); LDWm(0);
    STAB(As0); STWB(Ws0);
    __syncthreads();

    for (int c = 0; c < 32; c++) {
        const int cur = c & 1;
        float* Acur = cur ? As1 : As0;
        float* Wcur = cur ? Ws1 : Ws0;
        float* Anxt = cur ? As0 : As1;
        float* Wnxt = cur ? Ws0 : Ws1;

        if (c < 31) { LDA(32*(c+1)); LDWm(32*(c+1)); }

#pragma unroll
        for (int ks = 0; ks < 4; ks++) {
            float2 a0 = *(const float2*)&Acur[(m0w + g     )*PPITCH + 8*ks + 2*tig];
            float2 a1 = *(const float2*)&Acur[(m0w + g +  8)*PPITCH + 8*ks + 2*tig];
            float2 a2 = *(const float2*)&Acur[(m0w + g + 16)*PPITCH + 8*ks + 2*tig];
            float2 a3 = *(const float2*)&Acur[(m0w + g + 24)*PPITCH + 8*ks + 2*tig];
            uint32_t af0[4] = { __float_as_uint(a0.x), __float_as_uint(a1.x),
                                __float_as_uint(a0.y), __float_as_uint(a1.y) };
            uint32_t af1[4] = { __float_as_uint(a2.x), __float_as_uint(a3.x),
                                __float_as_uint(a2.y), __float_as_uint(a3.y) };
#pragma unroll
            for (int n = 0; n < 8; n++) {
                uint32_t b0 = __float_as_uint(Wcur[(8*ks + tig    )*72 + 8*n + g]);
                uint32_t b1 = __float_as_uint(Wcur[(8*ks + tig + 4)*72 + 8*n + g]);
                mma8(acc[0][n], af0, b0, b1);
                mma8(acc[1][n], af1, b0, b1);
            }
        }
        if (c < 31) { STAB(Anxt); STWB(Wnxt); }
        __syncthreads();
    }

#pragma unroll
    for (int mi = 0; mi < 2; mi++) {
        const int rb = row0 + m0w + mi*16;
#pragma unroll
        for (int n = 0; n < 8; n++) {
            *(float2*)(out + (size_t)(rb + g    )*HSd + 8*n + 2*tig) =
                make_float2(tfv(acc[mi][n][0]), tfv(acc[mi][n][1]));
            *(float2*)(out + (size_t)(rb + g + 8)*HSd + 8*n + 2*tig) =
                make_float2(tfv(acc[mi][n][2]), tfv(acc[mi][n][3]));
        }
    }
#undef LDA
#undef LDWm
#undef STAB
#undef STWB
}

// ---------------------------------------------------------------------------
// Split-KV flash attention — 128-row Q tiles, 8 warps, double-buffered
// cp.async K/V/mask pipeline. Fragment math identical to r12.
// Smem: P 128x68, K 2x64x68, V 2x64x72, msk 2x64 = 104.5 KB -> 2 CTAs/SM.
// One __syncthreads + one wait_group per tile; P is warp-private.
// ---------------------------------------------------------------------------
__global__ __launch_bounds__(256, 2)
void attn_kernel(const int* __restrict__ mask, float* __restrict__ out)
{
    extern __shared__ float asm_[];
    float* Pb  = asm_;                        // 128*68
    float* Ks0 = asm_ + 128*68;               // 64*68
    float* Ks1 = Ks0 + 64*68;
    float* Vs0 = Ks1 + 64*68;                 // 64*72
    float* Vs1 = Vs0 + 64*72;
    int*   msk = (int*)(Vs1 + 64*72);         // [2][64]

    const int i = blockIdx.x;
    const int b = i & 7;
    const int r = 39 - (i >> 3);              // heavy (large qb) first
    int qb, chunk;
    if (r < 4)       { qb = r;                        chunk = 0; }
    else if (r < 12) { int t = r - 4;  qb = 4  + (t >> 1); chunk = t & 1; }
    else if (r < 24) { int t = r - 12; qb = 8  + t/3;      chunk = t - 3*(t/3); }
    else             { int t = r - 24; qb = 12 + (t >> 2); chunk = t & 3; }
    const int nch   = (2*qb + 9) >> 3;        // 1..4
    const int kb_lo = chunk * 8;
    const int kb_hi = min(kb_lo + 8, 2*qb + 2);

    const int q0   = qb * 128;
    const int tid  = threadIdx.x;
    const int wid  = tid >> 5;
    const int lane = tid & 31;
    const int g    = lane >> 2;
    const int tig  = lane & 3;
    const int m0w  = wid * 16;

#define ISSUE(kb, buf)                                                        \
    { const float* kg = g_k + (size_t)(b*Tt + (kb)*64)*HSd;                   \
      const float* vg = g_v + (size_t)(b*Tt + (kb)*64)*HSd;                   \
      float* kd = (buf) ? Ks1 : Ks0;                                          \
      float* vd = (buf) ? Vs1 : Vs0;                                          \
      _Pragma("unroll") for (int t4 = 0; t4 < 4; t4++) {                      \
          int t = tid + 256*t4;                                               \
          int rr = t >> 4, c4 = (t & 15) << 2;                                \
          cp16((uint32_t)__cvta_generic_to_shared(&kd[rr*68 + c4]),           \
               kg + rr*HSd + c4);                                             \
          cp16((uint32_t)__cvta_generic_to_shared(&vd[rr*72 + c4]),           \
               vg + rr*HSd + c4);                                             \
      }                                                                       \
      if (tid < 16)                                                           \
          cp16((uint32_t)__cvta_generic_to_shared(&msk[(buf)*64 + tid*4]),    \
               mask + b*Tt + (kb)*64 + tid*4);                                \
      CP_COMMIT(); }

    uint32_t qf[8][4];
    const float* qbase = g_q + (size_t)(b*Tt + q0 + m0w)*HSd;
#pragma unroll
    for (int k = 0; k < 8; k++) {
        qf[k][0] = __float_as_uint(qbase[(g    )*HSd + 8*k + tig    ]);
        qf[k][1] = __float_as_uint(qbase[(g + 8)*HSd + 8*k + tig    ]);
        qf[k][2] = __float_as_uint(qbase[(g    )*HSd + 8*k + tig + 4]);
        qf[k][3] = __float_as_uint(qbase[(g + 8)*HSd + 8*k + tig + 4]);
    }

    float o[8][4];
#pragma unroll
    for (int n = 0; n < 8; n++)
#pragma unroll
        for (int j = 0; j < 4; j++) o[n][j] = 0.f;
    float mr0 = -1e30f, mr1 = -1e30f, lr0 = 0.f, lr1 = 0.f;

    const float scale2 = 0.125f * 1.4426950408889634f;
    const int row0g = q0 + m0w + g;
    const int row1g = row0g + 8;

    ISSUE(kb_lo, 0);

    for (int kb = kb_lo; kb < kb_hi; kb++) {
        const int k0 = kb * 64;
        const int cur = (kb - kb_lo) & 1;
        const float* Kc = cur ? Ks1 : Ks0;
        const float* Vc = cur ? Vs1 : Vs0;
        const int*   mc = msk + cur*64;

        CP_WAIT0();          // tile kb arrived (this thread's copies)
        __syncthreads();     // CTA-wide visibility; all warps done with buf cur^1

        if (kb + 1 < kb_hi) ISSUE(kb + 1, cur ^ 1);

        // ---- S = Q K^T ----
        float s[8][4];
#pragma unroll
        for (int n = 0; n < 8; n++)
#pragma unroll
            for (int j = 0; j < 4; j++) s[n][j] = 0.f;
#pragma unroll
        for (int k = 0; k < 8; k++) {
#pragma unroll
            for (int n = 0; n < 8; n++) {
                uint32_t b0 = __float_as_uint(Kc[(8*n + g)*68 + 8*k + tig    ]);
                uint32_t b1 = __float_as_uint(Kc[(8*n + g)*68 + 8*k + tig + 4]);
                mma8(s[n], qf[k], b0, b1);
            }
        }

        // ---- scale (log2) + causal/pad mask ----
        const bool diag = (k0 >= q0);
#pragma unroll
        for (int n = 0; n < 8; n++) {
            int cl = 8*n + 2*tig;
            int2 mm = *(const int2*)&mc[cl];
            int c0 = k0 + cl, c1 = c0 + 1;
            bool v00 = (mm.x != 0) && (!diag || c0 <= row0g);
            bool v01 = (mm.y != 0) && (!diag || c1 <= row0g);
            bool v10 = (mm.x != 0) && (!diag || c0 <= row1g);
            bool v11 = (mm.y != 0) && (!diag || c1 <= row1g);
            s[n][0] = v00 ? s[n][0]*scale2 : -1e30f;
            s[n][1] = v01 ? s[n][1]*scale2 : -1e30f;
            s[n][2] = v10 ? s[n][2]*scale2 : -1e30f;
            s[n][3] = v11 ? s[n][3]*scale2 : -1e30f;
        }

        // ---- online softmax, base-2 ----
        {
            float m0 = -1e30f, m1 = -1e30f;
#pragma unroll
            for (int n = 0; n < 8; n++) {
                m0 = fmaxf(m0, fmaxf(s[n][0], s[n][1]));
                m1 = fmaxf(m1, fmaxf(s[n][2], s[n][3]));
            }
#pragma unroll
            for (int off = 1; off < 4; off <<= 1) {
                m0 = fmaxf(m0, __shfl_xor_sync(0xffffffffu, m0, off));
                m1 = fmaxf(m1, __shfl_xor_sync(0xffffffffu, m1, off));
            }
            float mn0 = fmaxf(mr0, m0), mn1 = fmaxf(mr1, m1);
            float al0 = ex2(mr0 - mn0), al1 = ex2(mr1 - mn1);
            float ls0 = 0.f, ls1 = 0.f;
#pragma unroll
            for (int n = 0; n < 8; n++) {
                s[n][0] = ex2(s[n][0] - mn0);
                s[n][1] = ex2(s[n][1] - mn0);
                s[n][2] = ex2(s[n][2] - mn1);
                s[n][3] = ex2(s[n][3] - mn1);
                ls0 += s[n][0] + s[n][1];
                ls1 += s[n][2] + s[n][3];
            }
#pragma unroll
            for (int off = 1; off < 4; off <<= 1) {
                ls0 += __shfl_xor_sync(0xffffffffu, ls0, off);
                ls1 += __shfl_xor_sync(0xffffffffu, ls1, off);
            }
            lr0 = lr0*al0 + ls0;  mr0 = mn0;
            lr1 = lr1*al1 + ls1;  mr1 = mn1;
#pragma unroll
            for (int n = 0; n < 8; n++) {
                o[n][0] *= al0; o[n][1] *= al0;
                o[n][2] *= al1; o[n][3] *= al1;
            }
        }

        // ---- P (tf32) into own rows of Pb; warp-private, no CTA sync ----
#pragma unroll
        for (int n = 0; n < 8; n++) {
            float2 p0 = make_float2(tfv(s[n][0]), tfv(s[n][1]));
            float2 p1 = make_float2(tfv(s[n][2]), tfv(s[n][3]));
            *(float2*)&Pb[(m0w + g    )*68 + 8*n + 2*tig] = p0;
            *(float2*)&Pb[(m0w + g + 8)*68 + 8*n + 2*tig] = p1;
        }
        __syncwarp();

        // ---- O += P V ----
#pragma unroll
        for (int k = 0; k < 8; k++) {
            uint32_t af[4];
            af[0] = __float_as_uint(Pb[(m0w + g    )*68 + 8*k + tig    ]);
            af[1] = __float_as_uint(Pb[(m0w + g + 8)*68 + 8*k + tig    ]);
            af[2] = __float_as_uint(Pb[(m0w + g    )*68 + 8*k + tig + 4]);
            af[3] = __float_as_uint(Pb[(m0w + g + 8)*68 + 8*k + tig + 4]);
#pragma unroll
            for (int n = 0; n < 8; n++) {
                uint32_t b0 = __float_as_uint(Vc[(8*k + tig    )*72 + 8*n + g]);
                uint32_t b1 = __float_as_uint(Vc[(8*k + tig + 4)*72 + 8*n + g]);
                mma8(o[n], af, b0, b1);
            }
        }
    }

    // ---- epilogue ----
    if (nch == 1) {
        const float inv0 = 1.0f / lr0, inv1 = 1.0f / lr1;
        float* obase = out + (size_t)(b*Tt + q0 + m0w)*HSd;
#pragma unroll
        for (int n = 0; n < 8; n++) {
            *(float2*)(obase + (g    )*HSd + 8*n + 2*tig) =
                make_float2(o[n][0]*inv0, o[n][1]*inv0);
            *(float2*)(obase + (g + 8)*HSd + 8*n + 2*tig) =
                make_float2(o[n][2]*inv1, o[n][3]*inv1);
        }
    } else {
        const size_t idx = (size_t)((b*NQT + qb)*MAXCH + chunk);
        float* pO = g_pO + idx*8192;
#pragma unroll
        for (int n = 0; n < 8; n++) {
            *(float2*)&pO[(m0w + g    )*64 + 8*n + 2*tig] =
                make_float2(o[n][0], o[n][1]);
            *(float2*)&pO[(m0w + g + 8)*64 + 8*n + 2*tig] =
                make_float2(o[n][2], o[n][3]);
        }
        if (tig == 0) {
            g_pm[idx*128 + m0w + g    ] = mr0;
            g_pl[idx*128 + m0w + g    ] = lr0;
            g_pm[idx*128 + m0w + g + 8] = mr1;
            g_pl[idx*128 + m0w + g + 8] = lr1;
        }
    }
#undef ISSUE
}

// ---------------------------------------------------------------------------
// Combine partials for qb >= 4 (2..4 chunks). Grid (12, 8) x 512 thr.
// ---------------------------------------------------------------------------
__global__ __launch_bounds__(512)
void combine_kernel(float* __restrict__ out)
{
    const int qb  = 4 + blockIdx.x;
    const int b   = blockIdx.y;
    const int nch = (2*qb + 9) >> 3;
    const int t   = threadIdx.x;
    const int row = t >> 2;
    const int oc  = (t & 3) * 16;
    const int base = (b*NQT + qb)*MAXCH;

    float mg = -1e30f;
    for (int i = 0; i < nch; i++)
        mg = fmaxf(mg, g_pm[(base + i)*128 + row]);

    float l = 0.f;
    float4 acc[4];
#pragma unroll
    for (int j = 0; j < 4; j++) acc[j] = make_float4(0.f, 0.f, 0.f, 0.f);

    for (int i = 0; i < nch; i++) {
        float w = ex2(g_pm[(base + i)*128 + row] - mg);
        l += w * g_pl[(base + i)*128 + row];
        const float4* src = (const float4*)&g_pO[(size_t)(base + i)*8192 + row*64 + oc];
#pragma unroll
        for (int j = 0; j < 4; j++) {
            float4 v = src[j];
            acc[j].x += w*v.x; acc[j].y += w*v.y;
            acc[j].z += w*v.z; acc[j].w += w*v.w;
        }
    }

    const float inv = 1.0f / l;
    float4* dst = (float4*)(out + (size_t)(b*Tt + qb*128 + row)*HSd + oc);
#pragma unroll
    for (int j = 0; j < 4; j++)
        dst[j] = make_float4(acc[j].x*inv, acc[j].y*inv, acc[j].z*inv, acc[j].w*inv);
}

// ---------------------------------------------------------------------------
extern "C" void kernel_launch(void* const* d_in, const int* in_sizes, int n_in,
                              void* d_out, int out_size)
{
    const float* q_vec = (const float*)d_in[0];
    const float* k_vec = (const float*)d_in[1];
    const float* v_vec = (const float*)d_in[2];
    const int*   mask  = (const int*)  d_in[3];
    const float* Wq    = (const float*)d_in[4];
    const float* Wk    = (const float*)d_in[5];
    const float* Wv    = (const float*)d_in[6];
    float* out = (float*)d_out;

    const int proj_smem = (2*128*PPITCH + 2*32*72) * 4;               // 59392 B
    cudaFuncSetAttribute(proj_kernel,
                         cudaFuncAttributeMaxDynamicSharedMemorySize, proj_smem);
    const int attn_smem = (128*68 + 2*64*68 + 2*64*72) * 4 + 2*64*4;  // 107008 B
    cudaFuncSetAttribute(attn_kernel,
                         cudaFuncAttributeMaxDynamicSharedMemorySize, attn_smem);

    prep_w<<<dim3(Cc*HSd/1024, 3), 256>>>(Wq, Wk, Wv);
    proj_kernel<<<dim3(Mrows/128, 3), 128, proj_smem>>>(q_vec, k_vec, v_vec);
    attn_kernel<<<320, 256, attn_smem>>>(mask, out);
    combine_kernel<<<dim3(12, 8), 512>>>(out);
}